// round 4
// baseline (speedup 1.0000x reference)
#include <cuda_runtime.h>
#include <cstdint>

#define HDIM  1024
#define BATCH 2048
#define SEQL  96
#define VOCAB 96
#define NBH   (BATCH * HDIM)

// -------- device scratch (allocation-free rule: __device__ globals) --------
__device__ float g_h0[2][NBH];            // double-buffered layer-0 state
__device__ float g_hs[SEQL][NBH];         // all layer-1 states (FC input + recurrence)
__device__ float g_logits[(size_t)SEQL * BATCH * VOCAB];
__device__ float g_bias0[HDIM];
__device__ float g_bias1[HDIM];

typedef unsigned long long u64;

__device__ __forceinline__ void fma2(u64& d, u64 a, u64 b) {
    asm("fma.rn.f32x2 %0, %1, %2, %0;" : "+l"(d) : "l"(a), "l"(b));
}
__device__ __forceinline__ float pk_lo(u64 v) { return __uint_as_float((unsigned)(v & 0xffffffffull)); }
__device__ __forceinline__ float pk_hi(u64 v) { return __uint_as_float((unsigned)(v >> 32)); }

// ---------------------------------------------------------------------------
// prep: fuse biases, zero initial h0
// ---------------------------------------------------------------------------
__global__ void prep_kernel(const float* __restrict__ b0a, const float* __restrict__ b0b,
                            const float* __restrict__ b1a, const float* __restrict__ b1b) {
    int i = blockIdx.x * blockDim.x + threadIdx.x;
    if (i < HDIM) {
        g_bias0[i] = b0a[i] + b0b[i];
        g_bias1[i] = b1a[i] + b1b[i];
    }
    int stride = gridDim.x * blockDim.x;
    for (int j = i; j < NBH; j += stride) g_h0[0][j] = 0.0f;
}

// ---------------------------------------------------------------------------
// Fused GEMM + tanh:
//   C[m,n] = tanh( sum_k A0[m,k]*W0[n,k]  (+ sum_k A1[m,k]*W1[n,k] if DUAL)
//                  (+ x[m*SEQL+t]*wcol[n] if HAS_X)  + bias[n] )
// M=2048, N=1024, K=1024 (x2 if DUAL). 128x128 tile, 256 threads, 8x8 micro.
// K packed into even/odd pairs -> fma.rn.f32x2 (2x fp32 FMA rate on sm_103a).
// ---------------------------------------------------------------------------
template<bool HAS_X, bool DUAL>
__global__ void __launch_bounds__(256, 1)
gemm_tanh_kernel(const float* __restrict__ A0, const float* __restrict__ W0,
                 const float* __restrict__ A1, const float* __restrict__ W1,
                 float* __restrict__ C,
                 const float* __restrict__ x, const float* __restrict__ wcol,
                 const float* __restrict__ bias, int t)
{
    __shared__ __align__(16) float2 As[4][128];   // [k-pair][m]
    __shared__ __align__(16) float2 Bs[4][128];   // [k-pair][n]

    const int tid  = threadIdx.x;
    const int m0   = blockIdx.y << 7;
    const int n0   = blockIdx.x << 7;
    const int tx   = tid & 15;
    const int ty   = tid >> 4;
    const int lrow = tid >> 1;        // 0..127
    const int lcol = (tid & 1) << 2;  // 0 or 4
    const int kp0  = lcol >> 1;       // 0 or 2

    u64 acc[8][8];
    #pragma unroll
    for (int i = 0; i < 8; ++i)
        #pragma unroll
        for (int j = 0; j < 8; ++j) acc[i][j] = 0ull;

    const int npass = DUAL ? 2 : 1;
    for (int pass = 0; pass < npass; ++pass) {
        const float* A  = (pass == 0) ? A0 : A1;
        const float* W  = (pass == 0) ? W0 : W1;
        const float* Ap = A + (size_t)(m0 + lrow) * HDIM + lcol;
        const float* Wp = W + (size_t)(n0 + lrow) * HDIM + lcol;

        for (int kt = 0; kt < HDIM; kt += 8) {
            float4 av = __ldg((const float4*)(Ap + kt));
            float4 bv = __ldg((const float4*)(Wp + kt));
            __syncthreads();
            As[kp0    ][lrow] = make_float2(av.x, av.y);
            As[kp0 + 1][lrow] = make_float2(av.z, av.w);
            Bs[kp0    ][lrow] = make_float2(bv.x, bv.y);
            Bs[kp0 + 1][lrow] = make_float2(bv.z, bv.w);
            __syncthreads();

            #pragma unroll
            for (int kp = 0; kp < 4; ++kp) {
                u64 a2[8], b2[8];
                {
                    ulonglong2 p0 = *(const ulonglong2*)&As[kp][ty * 4];
                    ulonglong2 p1 = *(const ulonglong2*)&As[kp][ty * 4 + 2];
                    ulonglong2 p2 = *(const ulonglong2*)&As[kp][64 + ty * 4];
                    ulonglong2 p3 = *(const ulonglong2*)&As[kp][64 + ty * 4 + 2];
                    a2[0] = p0.x; a2[1] = p0.y; a2[2] = p1.x; a2[3] = p1.y;
                    a2[4] = p2.x; a2[5] = p2.y; a2[6] = p3.x; a2[7] = p3.y;
                }
                {
                    ulonglong2 q0 = *(const ulonglong2*)&Bs[kp][tx * 4];
                    ulonglong2 q1 = *(const ulonglong2*)&Bs[kp][tx * 4 + 2];
                    ulonglong2 q2 = *(const ulonglong2*)&Bs[kp][64 + tx * 4];
                    ulonglong2 q3 = *(const ulonglong2*)&Bs[kp][64 + tx * 4 + 2];
                    b2[0] = q0.x; b2[1] = q0.y; b2[2] = q1.x; b2[3] = q1.y;
                    b2[4] = q2.x; b2[5] = q2.y; b2[6] = q3.x; b2[7] = q3.y;
                }
                #pragma unroll
                for (int i = 0; i < 8; ++i)
                    #pragma unroll
                    for (int j = 0; j < 8; ++j)
                        fma2(acc[i][j], a2[i], b2[j]);
            }
        }
    }

    // Epilogue: reduce packed lanes, add bias (+ x outer term), tanh, store.
    #pragma unroll
    for (int i = 0; i < 8; ++i) {
        int row = m0 + ((i < 4) ? (ty * 4 + i) : (64 + ty * 4 + (i - 4)));
        float xv = 0.0f;
        if (HAS_X) xv = __ldg(&x[(size_t)row * SEQL + t]);
        #pragma unroll
        for (int j = 0; j < 8; ++j) {
            int col = n0 + ((j < 4) ? (tx * 4 + j) : (64 + tx * 4 + (j - 4)));
            float s = pk_lo(acc[i][j]) + pk_hi(acc[i][j]) + bias[col];
            if (HAS_X) s += xv * wcol[col];
            C[(size_t)row * HDIM + col] = tanhf(s);
        }
    }
}

// ---------------------------------------------------------------------------
// FC head: logits[r, v] = g_hs_flat[r, :] . fc_W[v, :] + fc_b[v]
// r = t*BATCH + b  (L*B = 196608 rows). Block = (96, 8): 8 rows, 1 v/thread.
// ---------------------------------------------------------------------------
__global__ void __launch_bounds__(768)
fc_kernel(const float* __restrict__ fcW, const float* __restrict__ fcb)
{
    __shared__ float hrow[8][HDIM];
    const float* hbase = &g_hs[0][0];
    int r0  = blockIdx.x * 8;
    int tid = threadIdx.y * 96 + threadIdx.x;

    for (int i = tid; i < 8 * HDIM; i += 768) {
        int rr = i >> 10, kk = i & 1023;
        hrow[rr][kk] = hbase[(size_t)(r0 + rr) * HDIM + kk];
    }
    __syncthreads();

    int v = threadIdx.x, ry = threadIdx.y;
    const float* w = fcW + (size_t)v * HDIM;
    float acc = 0.0f;
    #pragma unroll 4
    for (int k = 0; k < HDIM; k += 4) {
        float4 wv = __ldg((const float4*)(w + k));
        acc = fmaf(hrow[ry][k],     wv.x, acc);
        acc = fmaf(hrow[ry][k + 1], wv.y, acc);
        acc = fmaf(hrow[ry][k + 2], wv.z, acc);
        acc = fmaf(hrow[ry][k + 3], wv.w, acc);
    }
    g_logits[(size_t)(r0 + ry) * VOCAB + v] = acc + __ldg(&fcb[v]);
}

// ---------------------------------------------------------------------------
// Sequential probability patch. One warp per batch element, 96 steps.
// argmax ties break to lowest index (matches jnp.argmax).
// ---------------------------------------------------------------------------
__device__ __forceinline__ int warp_argmax3(float v0, float v1, float v2, int lane) {
    float mv = v0; int mi = lane;
    if (v1 > mv) { mv = v1; mi = lane + 32; }
    if (v2 > mv) { mv = v2; mi = lane + 64; }
    #pragma unroll
    for (int off = 16; off; off >>= 1) {
        float ov = __shfl_xor_sync(0xffffffffu, mv, off);
        int   oi = __shfl_xor_sync(0xffffffffu, mi, off);
        if (ov > mv || (ov == mv && oi < mi)) { mv = ov; mi = oi; }
    }
    return mi;
}

__global__ void adjust_kernel(float* __restrict__ out) {
    int gw   = (blockIdx.x * blockDim.x + threadIdx.x) >> 5;
    int lane = threadIdx.x & 31;
    if (gw >= BATCH) return;
    int b = gw;
    int prevarg = 0;

    for (int t = 0; t < SEQL; ++t) {
        const float* row = g_logits + ((size_t)t * BATCH + b) * VOCAB;
        float v0 = row[lane], v1 = row[lane + 32], v2 = row[lane + 64];

        int curarg = warp_argmax3(v0, v1, v2, lane);   // argmax of RAW row
        if (t > 0) {
            if (prevarg == 0 && curarg != 1 && lane == 1) v0 += 0.5f;           // U_IDX
            if (t == SEQL - 1 && curarg == 0 && lane == 0) v0 -= 0.5f;          // Q_IDX
        }
        float* o = out + ((size_t)b * SEQL + t) * VOCAB;
        o[lane] = v0; o[lane + 32] = v1; o[lane + 64] = v2;

        prevarg = warp_argmax3(v0, v1, v2, lane);      // argmax of ADJUSTED row
    }
}

// ---------------------------------------------------------------------------
// Final hidden states: out2 = [h0_final, h1_final], each [B, H]
// ---------------------------------------------------------------------------
__global__ void copy_hidden_kernel(float* __restrict__ out2) {
    int i = blockIdx.x * blockDim.x + threadIdx.x;
    if (i < NBH) {
        out2[i]       = g_h0[0][i];           // after 96 steps final h0 is buffer 0
        out2[NBH + i] = g_hs[SEQL - 1][i];
    }
}

// ---------------------------------------------------------------------------
extern "C" void kernel_launch(void* const* d_in, const int* in_sizes, int n_in,
                              void* d_out, int out_size)
{
    const float* x       = (const float*)d_in[0];
    const float* l0_Wih  = (const float*)d_in[1];   // (H, 1)
    const float* l0_Whh  = (const float*)d_in[2];   // (H, H)
    const float* l0_bih  = (const float*)d_in[3];
    const float* l0_bhh  = (const float*)d_in[4];
    const float* l1_Wih  = (const float*)d_in[5];
    const float* l1_Whh  = (const float*)d_in[6];
    const float* l1_bih  = (const float*)d_in[7];
    const float* l1_bhh  = (const float*)d_in[8];
    const float* fc_W    = (const float*)d_in[9];
    const float* fc_b    = (const float*)d_in[10];

    void* p;
    cudaGetSymbolAddress(&p, g_h0);    float* h0b = (float*)p;
    cudaGetSymbolAddress(&p, g_hs);    float* hsb = (float*)p;
    cudaGetSymbolAddress(&p, g_bias0); float* bias0 = (float*)p;
    cudaGetSymbolAddress(&p, g_bias1); float* bias1 = (float*)p;

    prep_kernel<<<1024, 256>>>(l0_bih, l0_bhh, l1_bih, l1_bhh);

    dim3 ggrid(HDIM / 128, BATCH / 128);   // (8, 16)
    for (int t = 0; t < SEQL; ++t) {
        float* h0_cur = h0b + (size_t)(t & 1) * NBH;
        float* h0_nxt = h0b + (size_t)((t & 1) ^ 1) * NBH;
        // layer 0: h0' = tanh(x_t * Wih0 + h0 @ Whh0^T + bias0)
        gemm_tanh_kernel<true, false><<<ggrid, 256>>>(
            h0_cur, l0_Whh, nullptr, nullptr, h0_nxt, x, l0_Wih, bias0, t);
        // layer 1: h1' = tanh(h0' @ Wih1^T + h1 @ Whh1^T + bias1)
        float* h1_out = hsb + (size_t)t * NBH;
        if (t == 0) {
            gemm_tanh_kernel<false, false><<<ggrid, 256>>>(
                h0_nxt, l1_Wih, nullptr, nullptr, h1_out, nullptr, nullptr, bias1, 0);
        } else {
            float* h1_prev = hsb + (size_t)(t - 1) * NBH;
            gemm_tanh_kernel<false, true><<<ggrid, 256>>>(
                h0_nxt, l1_Wih, h1_prev, l1_Whh, h1_out, nullptr, nullptr, bias1, 0);
        }
    }

    fc_kernel<<<(SEQL * BATCH) / 8, dim3(96, 8)>>>(fc_W, fc_b);

    float* out = (float*)d_out;
    adjust_kernel<<<BATCH / 8, 256>>>(out);
    copy_hidden_kernel<<<(NBH + 255) / 256, 256>>>(out + (size_t)BATCH * SEQL * VOCAB);
}

// round 6
// speedup vs baseline: 1.9191x; 1.9191x over previous
#include <cuda_runtime.h>
#include <cuda_fp16.h>
#include <cstdint>

#define HDIM  1024
#define BATCH 2048
#define SEQL  96
#define VOCAB 96
#define NBH   (BATCH * HDIM)
#define HH    ((size_t)HDIM * HDIM)

typedef unsigned int u32;

__device__ float g_h0f[NBH];
__device__ float g_hs[SEQL][NBH];
__device__ float g_logits[(size_t)SEQL * BATCH * VOCAB];
__device__ float g_bias0[HDIM];
__device__ float g_bias1[HDIM];
__device__ __half g_h0s[2][2ULL * NBH];   // [buf][split*NBH + b*H]
__device__ __half g_h1s[2][2ULL * NBH];
__device__ __half g_w0hh[2 * HH];         // [split*HH + n*H + k]
__device__ __half g_w1ih[2 * HH];
__device__ __half g_w1hh[2 * HH];

__device__ __forceinline__ u32 smem_u32(const void* p) {
    u32 a; asm("{ .reg .u64 t; cvta.to.shared.u64 t, %1; cvt.u32.u64 %0, t; }" : "=r"(a) : "l"(p));
    return a;
}
__device__ __forceinline__ void cpa16(u32 s, const void* g) {
    asm volatile("cp.async.cg.shared.global [%0], [%1], 16;" :: "r"(s), "l"(g) : "memory");
}
__device__ __forceinline__ void ldsm4(u32& r0, u32& r1, u32& r2, u32& r3, u32 a) {
    asm volatile("ldmatrix.sync.aligned.m8n8.x4.shared.b16 {%0,%1,%2,%3}, [%4];"
                 : "=r"(r0), "=r"(r1), "=r"(r2), "=r"(r3) : "r"(a));
}
__device__ __forceinline__ void mma16816(float* c, const u32* a, u32 b0, u32 b1) {
    asm volatile("mma.sync.aligned.m16n8k16.row.col.f32.f16.f16.f32 "
                 "{%0,%1,%2,%3}, {%4,%5,%6,%7}, {%8,%9}, {%0,%1,%2,%3};"
                 : "+f"(c[0]), "+f"(c[1]), "+f"(c[2]), "+f"(c[3])
                 : "r"(a[0]), "r"(a[1]), "r"(a[2]), "r"(a[3]), "r"(b0), "r"(b1));
}

__device__ __forceinline__ void split2(float v, __half* d, size_t j, size_t st) {
    __half a = __float2half_rn(v);
    d[j] = a;
    d[st + j] = __float2half_rn(v - __half2float(a));
}

__global__ void prep_kernel(const float* __restrict__ w0hh, const float* __restrict__ w1ih,
                            const float* __restrict__ w1hh,
                            const float* __restrict__ b0a, const float* __restrict__ b0b,
                            const float* __restrict__ b1a, const float* __restrict__ b1b) {
    size_t i = (size_t)blockIdx.x * blockDim.x + threadIdx.x;
    size_t st = (size_t)gridDim.x * blockDim.x;
    if (i < HDIM) { g_bias0[i] = b0a[i] + b0b[i]; g_bias1[i] = b1a[i] + b1b[i]; }
    for (size_t j = i; j < HH; j += st) {
        split2(w0hh[j], g_w0hh, j, HH);
        split2(w1ih[j], g_w1ih, j, HH);
        split2(w1hh[j], g_w1hh, j, HH);
    }
    __half z = __float2half_rn(0.0f);
    for (size_t j = i; j < 2ULL * NBH; j += st) { g_h0s[0][j] = z; g_h1s[0][j] = z; }
}

// -------------------- tensor-core RNN GEMM (mma.sync fp16x2) ----------------
// D[m,n] = sum_{(i,j) in {(0,0),(0,1),(1,0)}} A_i[m,:] . W_j[n,:]  (+dual pass)
// h = tanh(D + bias (+ x*wcol));  writes h fp32 and fp16x2 splits.
#define RSTRIDE 72              // smem row stride in halfs (64 data + 8 pad)
#define TILE_B  (128 * RSTRIDE * 2)      // 18432 bytes per tile
#define STAGE_B (4 * TILE_B)             // A0,A1,W0,W1
#define SMEM_BYTES (2 * STAGE_B)         // 147456

template<bool HAS_X, bool DUAL>
__global__ void __launch_bounds__(256, 1)
rnn_gemm_mma(const __half* __restrict__ A0s, const __half* __restrict__ W0s,
             const __half* __restrict__ A1s, const __half* __restrict__ W1s,
             float* __restrict__ Cf, __half* __restrict__ Cs,
             const float* __restrict__ bias,
             const float* __restrict__ x, const float* __restrict__ wcol, int t)
{
    extern __shared__ __align__(16) char smem[];
    const u32 sb = smem_u32(smem);
    const int tid = threadIdx.x, wid = tid >> 5, lane = tid & 31;
    const int m0 = blockIdx.y << 7, n0 = blockIdx.x << 7;
    const int wm = (wid & 3) * 32, wn = (wid >> 2) * 64;

    float c[2][8][4];
    #pragma unroll
    for (int i = 0; i < 2; ++i)
        #pragma unroll
        for (int j = 0; j < 8; ++j)
            #pragma unroll
            for (int q = 0; q < 4; ++q) c[i][j][q] = 0.0f;

    const int NC = DUAL ? 32 : 16;

    auto load_chunk = [&](int ch) {
        const __half* As = (DUAL && (ch >> 4)) ? A1s : A0s;
        const __half* Ws = (DUAL && (ch >> 4)) ? W1s : W0s;
        const int kc = ch & 15;                         // k-chunk: 64 halves
        const u32 stg = sb + (u32)(ch & 1) * STAGE_B;
        #pragma unroll
        for (int it = 0; it < 16; ++it) {
            int g = tid + it * 256;
            int tile = g >> 10, idx = g & 1023;
            int r = idx >> 3, seg = idx & 7;
            const __half* src;
            if (tile < 2)
                src = As + (size_t)tile * NBH + (size_t)(m0 + r) * HDIM + kc * 64 + seg * 8;
            else
                src = Ws + (size_t)(tile - 2) * HH + (size_t)(n0 + r) * HDIM + kc * 64 + seg * 8;
            cpa16(stg + (u32)tile * TILE_B + (u32)(r * RSTRIDE * 2 + seg * 16), src);
        }
        asm volatile("cp.async.commit_group;" ::: "memory");
    };

    load_chunk(0);
    load_chunk(1);

    for (int ch = 0; ch < NC; ++ch) {
        if (ch + 1 < NC) asm volatile("cp.async.wait_group 1;" ::: "memory");
        else             asm volatile("cp.async.wait_group 0;" ::: "memory");
        __syncthreads();

        const u32 stg = sb + (u32)(ch & 1) * STAGE_B;
        const int PI[3] = {0, 0, 1}, PJ[3] = {0, 1, 0};
        #pragma unroll
        for (int p = 0; p < 3; ++p) {
            const u32 Ab = stg + (u32)PI[p] * TILE_B;
            const u32 Wb = stg + (u32)(2 + PJ[p]) * TILE_B;
            #pragma unroll
            for (int ks = 0; ks < 4; ++ks) {
                const u32 kb = (u32)(ks * 32 + (lane >> 4) * 16);  // byte offset in row
                u32 a[2][4];
                #pragma unroll
                for (int mm = 0; mm < 2; ++mm)
                    ldsm4(a[mm][0], a[mm][1], a[mm][2], a[mm][3],
                          Ab + (u32)((wm + mm * 16 + (lane & 15)) * RSTRIDE * 2) + kb);
                #pragma unroll
                for (int ng = 0; ng < 4; ++ng) {
                    u32 b0, b1, b2, b3;
                    ldsm4(b0, b1, b2, b3,
                          Wb + (u32)((wn + ng * 16 + (lane & 15)) * RSTRIDE * 2) + kb);
                    #pragma unroll
                    for (int mm = 0; mm < 2; ++mm) {
                        mma16816(c[mm][ng * 2],     a[mm], b0, b2);
                        mma16816(c[mm][ng * 2 + 1], a[mm], b1, b3);
                    }
                }
            }
        }
        __syncthreads();
        if (ch + 2 < NC) load_chunk(ch + 2);
    }

    // ---- epilogue: bias (+x outer), tanh, store fp32 + fp16 splits ----
    const int nb = n0 + wn + (lane & 3) * 2;
    #pragma unroll
    for (int mm = 0; mm < 2; ++mm) {
        #pragma unroll
        for (int half8 = 0; half8 < 2; ++half8) {
            int m = m0 + wm + mm * 16 + (lane >> 2) + half8 * 8;
            float xv = HAS_X ? x[(size_t)m * SEQL + t] : 0.0f;
            #pragma unroll
            for (int nn = 0; nn < 8; ++nn) {
                #pragma unroll
                for (int q = 0; q < 2; ++q) {
                    int n = nb + nn * 8 + q;
                    float v = c[mm][nn][half8 * 2 + q] + bias[n];
                    if (HAS_X) v += xv * wcol[n];
                    float h = tanhf(v);
                    size_t off = (size_t)m * HDIM + n;
                    Cf[off] = h;
                    __half h0 = __float2half_rn(h);
                    Cs[off] = h0;
                    Cs[NBH + off] = __float2half_rn(h - __half2float(h0));
                }
            }
        }
    }
}

__global__ void __launch_bounds__(768)
fc_kernel(const float* __restrict__ fcW, const float* __restrict__ fcb)
{
    __shared__ __align__(16) float hrow[8][HDIM];
    const float* hbase = &g_hs[0][0];
    int r0 = blockIdx.x * 8;
    int tid = threadIdx.y * 96 + threadIdx.x;
    for (int i = tid; i < 8 * HDIM; i += 768) {
        int rr = i >> 10, kk = i & 1023;
        hrow[rr][kk] = hbase[(size_t)(r0 + rr) * HDIM + kk];
    }
    __syncthreads();
    int v = threadIdx.x, ry = threadIdx.y;
    const float* w = fcW + (size_t)v * HDIM;
    float acc = 0.0f;
    #pragma unroll 4
    for (int k = 0; k < HDIM; k += 4) {
        float4 wv = __ldg((const float4*)(w + k));
        acc = fmaf(hrow[ry][k], wv.x, acc);
        acc = fmaf(hrow[ry][k + 1], wv.y, acc);
        acc = fmaf(hrow[ry][k + 2], wv.z, acc);
        acc = fmaf(hrow[ry][k + 3], wv.w, acc);
    }
    g_logits[(size_t)(r0 + ry) * VOCAB + v] = acc + __ldg(&fcb[v]);
}

__device__ __forceinline__ int wargmax3(float v0, float v1, float v2, int lane) {
    float mv = v0; int mi = lane;
    if (v1 > mv) { mv = v1; mi = lane + 32; }
    if (v2 > mv) { mv = v2; mi = lane + 64; }
    #pragma unroll
    for (int o = 16; o; o >>= 1) {
        float ov = __shfl_xor_sync(0xffffffffu, mv, o);
        int oi = __shfl_xor_sync(0xffffffffu, mi, o);
        if (ov > mv || (ov == mv && oi < mi)) { mv = ov; mi = oi; }
    }
    return mi;
}

__global__ void adjust_kernel(float* __restrict__ out) {
    int gw = (blockIdx.x * blockDim.x + threadIdx.x) >> 5;
    int lane = threadIdx.x & 31;
    if (gw >= BATCH) return;
    int prevarg = 0;
    for (int t = 0; t < SEQL; ++t) {
        const float* row = g_logits + ((size_t)t * BATCH + gw) * VOCAB;
        float v0 = row[lane], v1 = row[lane + 32], v2 = row[lane + 64];
        int curarg = wargmax3(v0, v1, v2, lane);
        if (t > 0) {
            if (prevarg == 0 && curarg != 1 && lane == 1) v0 += 0.5f;
            if (t == SEQL - 1 && curarg == 0 && lane == 0) v0 -= 0.5f;
        }
        float* o = out + ((size_t)gw * SEQL + t) * VOCAB;
        o[lane] = v0; o[lane + 32] = v1; o[lane + 64] = v2;
        prevarg = wargmax3(v0, v1, v2, lane);
    }
}

__global__ void copy_hidden_kernel(float* __restrict__ out2) {
    int i = blockIdx.x * blockDim.x + threadIdx.x;
    if (i < NBH) { out2[i] = g_h0f[i]; out2[NBH + i] = g_hs[SEQL - 1][i]; }
}

extern "C" void kernel_launch(void* const* d_in, const int* in_sizes, int n_in,
                              void* d_out, int out_size)
{
    const float* x      = (const float*)d_in[0];
    const float* l0_Wih = (const float*)d_in[1];
    const float* l0_Whh = (const float*)d_in[2];
    const float* l0_bih = (const float*)d_in[3];
    const float* l0_bhh = (const float*)d_in[4];
    const float* l1_Wih = (const float*)d_in[5];
    const float* l1_Whh = (const float*)d_in[6];
    const float* l1_bih = (const float*)d_in[7];
    const float* l1_bhh = (const float*)d_in[8];
    const float* fc_W   = (const float*)d_in[9];
    const float* fc_b   = (const float*)d_in[10];

    void* p;
    cudaGetSymbolAddress(&p, g_h0f);   float* h0f = (float*)p;
    cudaGetSymbolAddress(&p, g_hs);    float* hsb = (float*)p;
    cudaGetSymbolAddress(&p, g_bias0); float* bias0 = (float*)p;
    cudaGetSymbolAddress(&p, g_bias1); float* bias1 = (float*)p;
    cudaGetSymbolAddress(&p, g_h0s);   __half* h0s = (__half*)p;
    cudaGetSymbolAddress(&p, g_h1s);   __half* h1s = (__half*)p;
    cudaGetSymbolAddress(&p, g_w0hh);  __half* w0hh = (__half*)p;
    cudaGetSymbolAddress(&p, g_w1ih);  __half* w1ih = (__half*)p;
    cudaGetSymbolAddress(&p, g_w1hh);  __half* w1hh = (__half*)p;

    cudaFuncSetAttribute(rnn_gemm_mma<true, false>,
                         cudaFuncAttributeMaxDynamicSharedMemorySize, SMEM_BYTES);
    cudaFuncSetAttribute(rnn_gemm_mma<false, true>,
                         cudaFuncAttributeMaxDynamicSharedMemorySize, SMEM_BYTES);

    prep_kernel<<<1024, 256>>>(l0_Whh, l1_Wih, l1_Whh, l0_bih, l0_bhh, l1_bih, l1_bhh);

    dim3 ggrid(HDIM / 128, BATCH / 128);   // (8, 16) = 128 CTAs
    const size_t SP = 2ULL * NBH;
    for (int t = 0; t < SEQL; ++t) {
        __half* h0_cur = h0s + (size_t)(t & 1) * SP;
        __half* h0_nxt = h0s + (size_t)((t & 1) ^ 1) * SP;
        __half* h1_cur = h1s + (size_t)(t & 1) * SP;
        __half* h1_nxt = h1s + (size_t)((t & 1) ^ 1) * SP;
        rnn_gemm_mma<true, false><<<ggrid, 256, SMEM_BYTES>>>(
            h0_cur, w0hh, nullptr, nullptr, h0f, h0_nxt, bias0, x, l0_Wih, t);
        rnn_gemm_mma<false, true><<<ggrid, 256, SMEM_BYTES>>>(
            h0_nxt, w1ih, h1_cur, w1hh, hsb + (size_t)t * NBH, h1_nxt,
            bias1, nullptr, nullptr, 0);
    }

    fc_kernel<<<(SEQL * BATCH) / 8, dim3(96, 8)>>>(fc_W, fc_b);

    float* out = (float*)d_out;
    adjust_kernel<<<BATCH / 8, 256>>>(out);
    copy_hidden_kernel<<<(NBH + 255) / 256, 256>>>(out + (size_t)BATCH * SEQL * VOCAB);
}

// round 7
// speedup vs baseline: 2.0231x; 1.0542x over previous
#include <cuda_runtime.h>
#include <cuda_fp16.h>
#include <cstdint>

#define HDIM  1024
#define BATCH 2048
#define SEQL  96
#define VOCAB 96
#define NBH   (BATCH * HDIM)
#define HH    ((size_t)HDIM * HDIM)

typedef unsigned int u32;

__device__ float g_h0f[NBH];
__device__ float g_hs[SEQL][NBH];
__device__ float g_logits[(size_t)SEQL * BATCH * VOCAB];
__device__ float g_bias0[HDIM];
__device__ float g_bias1[HDIM];
__device__ __half g_h0s[2][2ULL * NBH];   // [buf][split*NBH + b*H]
__device__ __half g_h1s[2][2ULL * NBH];
__device__ __half g_w0hh[2 * HH];         // [split*HH + n*H + k]
__device__ __half g_w1ih[2 * HH];
__device__ __half g_w1hh[2 * HH];

__device__ __forceinline__ u32 smem_u32(const void* p) {
    u32 a; asm("{ .reg .u64 t; cvta.to.shared.u64 t, %1; cvt.u32.u64 %0, t; }" : "=r"(a) : "l"(p));
    return a;
}
__device__ __forceinline__ void cpa16(u32 s, const void* g) {
    asm volatile("cp.async.cg.shared.global [%0], [%1], 16;" :: "r"(s), "l"(g) : "memory");
}
__device__ __forceinline__ void ldsm4(u32& r0, u32& r1, u32& r2, u32& r3, u32 a) {
    asm volatile("ldmatrix.sync.aligned.m8n8.x4.shared.b16 {%0,%1,%2,%3}, [%4];"
                 : "=r"(r0), "=r"(r1), "=r"(r2), "=r"(r3) : "r"(a));
}
__device__ __forceinline__ void mma16816(float* c, const u32* a, u32 b0, u32 b1) {
    asm volatile("mma.sync.aligned.m16n8k16.row.col.f32.f16.f16.f32 "
                 "{%0,%1,%2,%3}, {%4,%5,%6,%7}, {%8,%9}, {%0,%1,%2,%3};"
                 : "+f"(c[0]), "+f"(c[1]), "+f"(c[2]), "+f"(c[3])
                 : "r"(a[0]), "r"(a[1]), "r"(a[2]), "r"(a[3]), "r"(b0), "r"(b1));
}

__device__ __forceinline__ void split2(float v, __half* d, size_t j, size_t st) {
    __half a = __float2half_rn(v);
    d[j] = a;
    d[st + j] = __float2half_rn(v - __half2float(a));
}

__global__ void prep_kernel(const float* __restrict__ w0hh, const float* __restrict__ w1ih,
                            const float* __restrict__ w1hh,
                            const float* __restrict__ b0a, const float* __restrict__ b0b,
                            const float* __restrict__ b1a, const float* __restrict__ b1b) {
    size_t i = (size_t)blockIdx.x * blockDim.x + threadIdx.x;
    size_t st = (size_t)gridDim.x * blockDim.x;
    if (i < HDIM) { g_bias0[i] = b0a[i] + b0b[i]; g_bias1[i] = b1a[i] + b1b[i]; }
    for (size_t j = i; j < HH; j += st) {
        split2(w0hh[j], g_w0hh, j, HH);
        split2(w1ih[j], g_w1ih, j, HH);
        split2(w1hh[j], g_w1hh, j, HH);
    }
    __half z = __float2half_rn(0.0f);
    for (size_t j = i; j < 2ULL * NBH; j += st) { g_h0s[0][j] = z; g_h1s[0][j] = z; }
}

// -------------------- tensor-core RNN GEMM (mma.sync fp16x2) ----------------
// CTA tile 64(M) x 128(N), 256 threads = 8 warps of 32x32, 2 CTAs/SM.
// D = sum_{(i,j) in {(0,0),(0,1),(1,0)}} A_i @ W_j^T (+dual pass over 2nd ops)
// h = tanh(D + bias (+ x*wcol)); writes optional fp32 h + fp16x2 splits.
#define RSB   144                 // row stride bytes (72 halfs: 64 data + 8 pad)
#define A_TB  (64 * RSB)          // 9216 B per A tile
#define W_TB  (128 * RSB)         // 18432 B per W tile
#define STG_B (2 * A_TB + 2 * W_TB)   // 55296 B per stage
#define SMEM_BYTES (2 * STG_B)        // 110592

template<bool HAS_X, bool DUAL>
__global__ void __launch_bounds__(256, 2)
rnn_gemm_mma(const __half* __restrict__ A0s, const __half* __restrict__ W0s,
             const __half* __restrict__ A1s, const __half* __restrict__ W1s,
             float* __restrict__ Cf, __half* __restrict__ Cs,
             const float* __restrict__ bias,
             const float* __restrict__ x, const float* __restrict__ wcol, int t)
{
    extern __shared__ __align__(16) char smem[];
    const u32 sb = smem_u32(smem);
    const int tid = threadIdx.x, wid = tid >> 5, lane = tid & 31;
    const int m0 = blockIdx.y << 6, n0 = blockIdx.x << 7;
    const int wm = (wid & 1) * 32, wn = (wid >> 1) * 32;

    float c[2][4][4];
    #pragma unroll
    for (int i = 0; i < 2; ++i)
        #pragma unroll
        for (int j = 0; j < 4; ++j)
            #pragma unroll
            for (int q = 0; q < 4; ++q) c[i][j][q] = 0.0f;

    const int NC = DUAL ? 32 : 16;

    auto load_chunk = [&](int ch) {
        const __half* As = (DUAL && (ch >> 4)) ? A1s : A0s;
        const __half* Ws = (DUAL && (ch >> 4)) ? W1s : W0s;
        const int kc = (ch & 15) * 64;
        const u32 stg = sb + (u32)(ch & 1) * STG_B;
        #pragma unroll
        for (int it = 0; it < 12; ++it) {
            int g = tid + it * 256;
            const __half* src; u32 dst;
            if (g < 1024) {                       // A: 2 tiles x 64 rows x 8 segs
                int tile = g >> 9, idx = g & 511, r = idx >> 3, seg = idx & 7;
                src = As + (size_t)tile * NBH + (size_t)(m0 + r) * HDIM + kc + seg * 8;
                dst = stg + (u32)tile * A_TB + (u32)(r * RSB + seg * 16);
            } else {                              // W: 2 tiles x 128 rows x 8 segs
                int g2 = g - 1024;
                int tile = g2 >> 10, idx = g2 & 1023, r = idx >> 3, seg = idx & 7;
                src = Ws + (size_t)tile * HH + (size_t)(n0 + r) * HDIM + kc + seg * 8;
                dst = stg + 2 * A_TB + (u32)tile * W_TB + (u32)(r * RSB + seg * 16);
            }
            cpa16(dst, src);
        }
        asm volatile("cp.async.commit_group;" ::: "memory");
    };

    load_chunk(0);
    load_chunk(1);

    for (int ch = 0; ch < NC; ++ch) {
        if (ch + 1 < NC) asm volatile("cp.async.wait_group 1;" ::: "memory");
        else             asm volatile("cp.async.wait_group 0;" ::: "memory");
        __syncthreads();

        const u32 stg  = sb + (u32)(ch & 1) * STG_B;
        const u32 stgW = stg + 2 * A_TB;
        const int PI[3] = {0, 0, 1}, PJ[3] = {0, 1, 0};
        #pragma unroll
        for (int p = 0; p < 3; ++p) {
            const u32 Ab = stg  + (u32)PI[p] * A_TB;
            const u32 Wb = stgW + (u32)PJ[p] * W_TB;
            #pragma unroll
            for (int ks = 0; ks < 4; ++ks) {
                const u32 kb = (u32)(ks * 32 + (lane >> 4) * 16);
                u32 a[2][4], b[2][4];
                #pragma unroll
                for (int mm = 0; mm < 2; ++mm)
                    ldsm4(a[mm][0], a[mm][1], a[mm][2], a[mm][3],
                          Ab + (u32)((wm + mm * 16 + (lane & 15)) * RSB) + kb);
                #pragma unroll
                for (int ng = 0; ng < 2; ++ng)
                    ldsm4(b[ng][0], b[ng][1], b[ng][2], b[ng][3],
                          Wb + (u32)((wn + ng * 16 + (lane & 15)) * RSB) + kb);
                #pragma unroll
                for (int mm = 0; mm < 2; ++mm)
                    #pragma unroll
                    for (int ng = 0; ng < 2; ++ng) {
                        mma16816(c[mm][ng * 2],     a[mm], b[ng][0], b[ng][2]);
                        mma16816(c[mm][ng * 2 + 1], a[mm], b[ng][1], b[ng][3]);
                    }
            }
        }
        __syncthreads();
        if (ch + 2 < NC) load_chunk(ch + 2);
    }

    // ---- epilogue: bias (+x outer), tanh; vectorized stores ----
    #pragma unroll
    for (int mm = 0; mm < 2; ++mm) {
        #pragma unroll
        for (int h8 = 0; h8 < 2; ++h8) {
            int m = m0 + wm + mm * 16 + (lane >> 2) + h8 * 8;
            float xv = HAS_X ? x[(size_t)m * SEQL + t] : 0.0f;
            #pragma unroll
            for (int nn = 0; nn < 4; ++nn) {
                int n = n0 + wn + nn * 8 + (lane & 3) * 2;
                float v0 = c[mm][nn][h8 * 2]     + bias[n];
                float v1 = c[mm][nn][h8 * 2 + 1] + bias[n + 1];
                if (HAS_X) { v0 += xv * wcol[n]; v1 += xv * wcol[n + 1]; }
                float ha = tanhf(v0), hb = tanhf(v1);
                size_t off = (size_t)m * HDIM + n;
                if (Cf) *(float2*)(Cf + off) = make_float2(ha, hb);
                __half a0 = __float2half_rn(ha), b0 = __float2half_rn(hb);
                *(__half2*)(Cs + off) = __halves2half2(a0, b0);
                *(__half2*)(Cs + NBH + off) = __halves2half2(
                    __float2half_rn(ha - __half2float(a0)),
                    __float2half_rn(hb - __half2float(b0)));
            }
        }
    }
}

__global__ void __launch_bounds__(768)
fc_kernel(const float* __restrict__ fcW, const float* __restrict__ fcb)
{
    __shared__ __align__(16) float hrow[8][HDIM];
    const float* hbase = &g_hs[0][0];
    int r0 = blockIdx.x * 8;
    int tid = threadIdx.y * 96 + threadIdx.x;
    for (int i = tid; i < 8 * HDIM; i += 768) {
        int rr = i >> 10, kk = i & 1023;
        hrow[rr][kk] = hbase[(size_t)(r0 + rr) * HDIM + kk];
    }
    __syncthreads();
    int v = threadIdx.x, ry = threadIdx.y;
    const float* w = fcW + (size_t)v * HDIM;
    float acc = 0.0f;
    #pragma unroll 4
    for (int k = 0; k < HDIM; k += 4) {
        float4 wv = __ldg((const float4*)(w + k));
        acc = fmaf(hrow[ry][k], wv.x, acc);
        acc = fmaf(hrow[ry][k + 1], wv.y, acc);
        acc = fmaf(hrow[ry][k + 2], wv.z, acc);
        acc = fmaf(hrow[ry][k + 3], wv.w, acc);
    }
    g_logits[(size_t)(r0 + ry) * VOCAB + v] = acc + __ldg(&fcb[v]);
}

__device__ __forceinline__ int wargmax3(float v0, float v1, float v2, int lane) {
    float mv = v0; int mi = lane;
    if (v1 > mv) { mv = v1; mi = lane + 32; }
    if (v2 > mv) { mv = v2; mi = lane + 64; }
    #pragma unroll
    for (int o = 16; o; o >>= 1) {
        float ov = __shfl_xor_sync(0xffffffffu, mv, o);
        int oi = __shfl_xor_sync(0xffffffffu, mi, o);
        if (ov > mv || (ov == mv && oi < mi)) { mv = ov; mi = oi; }
    }
    return mi;
}

__global__ void adjust_kernel(float* __restrict__ out) {
    int gw = (blockIdx.x * blockDim.x + threadIdx.x) >> 5;
    int lane = threadIdx.x & 31;
    if (gw >= BATCH) return;
    int prevarg = 0;
    for (int t = 0; t < SEQL; ++t) {
        const float* row = g_logits + ((size_t)t * BATCH + gw) * VOCAB;
        float v0 = row[lane], v1 = row[lane + 32], v2 = row[lane + 64];
        int curarg = wargmax3(v0, v1, v2, lane);
        if (t > 0) {
            if (prevarg == 0 && curarg != 1 && lane == 1) v0 += 0.5f;
            if (t == SEQL - 1 && curarg == 0 && lane == 0) v0 -= 0.5f;
        }
        float* o = out + ((size_t)gw * SEQL + t) * VOCAB;
        o[lane] = v0; o[lane + 32] = v1; o[lane + 64] = v2;
        prevarg = wargmax3(v0, v1, v2, lane);
    }
}

__global__ void copy_hidden_kernel(float* __restrict__ out2) {
    int i = blockIdx.x * blockDim.x + threadIdx.x;
    if (i < NBH) { out2[i] = g_h0f[i]; out2[NBH + i] = g_hs[SEQL - 1][i]; }
}

extern "C" void kernel_launch(void* const* d_in, const int* in_sizes, int n_in,
                              void* d_out, int out_size)
{
    const float* x      = (const float*)d_in[0];
    const float* l0_Wih = (const float*)d_in[1];
    const float* l0_Whh = (const float*)d_in[2];
    const float* l0_bih = (const float*)d_in[3];
    const float* l0_bhh = (const float*)d_in[4];
    const float* l1_Wih = (const float*)d_in[5];
    const float* l1_Whh = (const float*)d_in[6];
    const float* l1_bih = (const float*)d_in[7];
    const float* l1_bhh = (const float*)d_in[8];
    const float* fc_W   = (const float*)d_in[9];
    const float* fc_b   = (const float*)d_in[10];

    void* p;
    cudaGetSymbolAddress(&p, g_h0f);   float* h0f = (float*)p;
    cudaGetSymbolAddress(&p, g_hs);    float* hsb = (float*)p;
    cudaGetSymbolAddress(&p, g_bias0); float* bias0 = (float*)p;
    cudaGetSymbolAddress(&p, g_bias1); float* bias1 = (float*)p;
    cudaGetSymbolAddress(&p, g_h0s);   __half* h0s = (__half*)p;
    cudaGetSymbolAddress(&p, g_h1s);   __half* h1s = (__half*)p;
    cudaGetSymbolAddress(&p, g_w0hh);  __half* w0hh = (__half*)p;
    cudaGetSymbolAddress(&p, g_w1ih);  __half* w1ih = (__half*)p;
    cudaGetSymbolAddress(&p, g_w1hh);  __half* w1hh = (__half*)p;

    cudaFuncSetAttribute(rnn_gemm_mma<true, false>,
                         cudaFuncAttributeMaxDynamicSharedMemorySize, SMEM_BYTES);
    cudaFuncSetAttribute(rnn_gemm_mma<false, true>,
                         cudaFuncAttributeMaxDynamicSharedMemorySize, SMEM_BYTES);

    prep_kernel<<<1024, 256>>>(l0_Whh, l1_Wih, l1_Whh, l0_bih, l0_bhh, l1_bih, l1_bhh);

    dim3 ggrid(HDIM / 128, BATCH / 64);   // (8, 32) = 256 CTAs
    const size_t SP = 2ULL * NBH;
    for (int t = 0; t < SEQL; ++t) {
        __half* h0_cur = h0s + (size_t)(t & 1) * SP;
        __half* h0_nxt = h0s + (size_t)((t & 1) ^ 1) * SP;
        __half* h1_cur = h1s + (size_t)(t & 1) * SP;
        __half* h1_nxt = h1s + (size_t)((t & 1) ^ 1) * SP;
        rnn_gemm_mma<true, false><<<ggrid, 256, SMEM_BYTES>>>(
            h0_cur, w0hh, nullptr, nullptr,
            (t == SEQL - 1) ? h0f : nullptr, h0_nxt, bias0, x, l0_Wih, t);
        rnn_gemm_mma<false, true><<<ggrid, 256, SMEM_BYTES>>>(
            h0_nxt, w1ih, h1_cur, w1hh, hsb + (size_t)t * NBH, h1_nxt,
            bias1, nullptr, nullptr, 0);
    }

    fc_kernel<<<(SEQL * BATCH) / 8, dim3(96, 8)>>>(fc_W, fc_b);

    float* out = (float*)d_out;
    adjust_kernel<<<BATCH / 8, 256>>>(out);
    copy_hidden_kernel<<<(NBH + 255) / 256, 256>>>(out + (size_t)BATCH * SEQL * VOCAB);
}